// round 9
// baseline (speedup 1.0000x reference)
#include <cuda_runtime.h>
#include <cuda_fp16.h>
#include <mma.h>
#include <math.h>
#include <stdint.h>

using namespace nvcuda;

// ---------------- problem constants ----------------
constexpr int kB = 2, kS = 2048, kT = kB * kS;  // 4096 tokens
constexpr int kD = 768, kE = 4, kL = 2, kH = 3072;
constexpr float kEPS = 1e-6f;

// ---------------- GEMM tiling ----------------
constexpr int BM = 128, BN = 128, BK = 32;
constexpr int NSTG = 4;                          // cp.async ring stages
constexpr int MAXROWS = kT + kE * BM;            // 4608
constexpr int NT_MAX  = MAXROWS / BM;            // 36

constexpr int LDA = 40;    // halves per A row  (80B  -> conflict-free LDSM)
constexpr int LDB = 136;   // halves per B row  (272B -> conflict-free LDSM)
constexpr int A_ELE = BM * LDA;            // 5120 halves
constexpr int B_ELE = BK * LDB;            // 4352 halves
constexpr int STG_ELE = A_ELE + B_ELE;     // 9472 halves = 18944 B
constexpr int SMEM_BYTES = NSTG * STG_ELE * 2;   // 75776 B
constexpr int LDC_S = 20;

// ---------------- device scratch (no allocs allowed) ----------------
__device__ float  g_xbuf[(size_t)kT * kD];            // running residual (fp32)
__device__ __half g_hbuf[(size_t)kT * kD];            // layernorm output (fp16)
__device__ __half g_abuf[(size_t)MAXROWS * kH];       // gelu(GEMM1) output (fp16)
__device__ __half g_w1h[(size_t)kL * kE * kD * kH];   // W1 as fp16 [L,E,D,H]
__device__ __half g_w2h[(size_t)kL * kE * kH * kD];   // W2 as fp16 [L,E,H,D]
__device__ int    g_perm[MAXROWS];
__device__ int    g_cnt[kE];
__device__ int    g_fill[kE];
__device__ int    g_off[kE + 1];

// ---------------- cp.async helpers ----------------
__device__ __forceinline__ uint32_t smem_u32(const void* p) {
    return (uint32_t)__cvta_generic_to_shared(p);
}
__device__ __forceinline__ void cp_async16(void* smem, const void* gmem, int src_bytes) {
    asm volatile("cp.async.cg.shared.global [%0], [%1], 16, %2;\n"
                 :: "r"(smem_u32(smem)), "l"(gmem), "r"(src_bytes));
}
__device__ __forceinline__ void cp_commit() { asm volatile("cp.async.commit_group;\n"); }
template <int N>
__device__ __forceinline__ void cp_wait() {
    asm volatile("cp.async.wait_group %0;\n" :: "n"(N));
}

__device__ __forceinline__ float gelu_exact(float v) {
    return 0.5f * v * (1.0f + erff(v * 0.70710678118654752f));
}

// ---------------- routing ----------------
__global__ void route_init() {
    int t = blockIdx.x * blockDim.x + threadIdx.x;
    if (t < kE) { g_cnt[t] = 0; g_fill[t] = 0; }
    if (t < MAXROWS) g_perm[t] = -1;
}
__global__ void route_count(const int* __restrict__ eix) {
    int t = blockIdx.x * blockDim.x + threadIdx.x;
    if (t < kT) atomicAdd(&g_cnt[eix[t]], 1);
}
__global__ void route_offsets() {
    if (threadIdx.x == 0) {
        int o = 0;
        g_off[0] = 0;
        for (int e = 0; e < kE; e++) {
            o += ((g_cnt[e] + BM - 1) / BM) * BM;
            g_off[e + 1] = o;
        }
    }
}
__global__ void route_scatter(const int* __restrict__ eix) {
    int t = blockIdx.x * blockDim.x + threadIdx.x;
    if (t < kT) {
        int e = eix[t];
        int p = g_off[e] + atomicAdd(&g_fill[e], 1);
        g_perm[p] = t;
    }
}

__global__ void copy_x(const float4* __restrict__ src) {
    int i = blockIdx.x * blockDim.x + threadIdx.x;
    reinterpret_cast<float4*>(g_xbuf)[i] = src[i];
}

// ---------------- weight fp32 -> fp16 convert ----------------
__global__ void convert_w(const float4* __restrict__ src, __half* __restrict__ dst) {
    int i = blockIdx.x * blockDim.x + threadIdx.x;
    float4 v = src[i];
    __half2* d = reinterpret_cast<__half2*>(dst + (size_t)i * 4);
    d[0] = __floats2half2_rn(v.x, v.y);
    d[1] = __floats2half2_rn(v.z, v.w);
}

// ---------------- layernorm (fp32 math, fp16 output) ----------------
__device__ __forceinline__ float block_sum(float v) {
    __shared__ float sh[8];
    int lane = threadIdx.x & 31;
    int w = threadIdx.x >> 5;
#pragma unroll
    for (int o = 16; o > 0; o >>= 1) v += __shfl_xor_sync(0xffffffffu, v, o);
    __syncthreads();
    if (lane == 0) sh[w] = v;
    __syncthreads();
    float r = sh[lane & 7];
#pragma unroll
    for (int o = 4; o > 0; o >>= 1) r += __shfl_xor_sync(0xffffffffu, r, o);
    return r;
}

__global__ void ln_kernel(const float* __restrict__ lng, const float* __restrict__ lnb) {
    int tok = blockIdx.x;
    const float* xr = g_xbuf + (size_t)tok * kD;
    int t = threadIdx.x;
    float v0 = xr[t], v1 = xr[t + 256], v2 = xr[t + 512];
    float mu = block_sum(v0 + v1 + v2) * (1.0f / kD);
    float d0 = v0 - mu, d1 = v1 - mu, d2 = v2 - mu;
    float var = block_sum(d0 * d0 + d1 * d1 + d2 * d2) * (1.0f / kD);
    float rs = rsqrtf(var + kEPS);
    __half* hr = g_hbuf + (size_t)tok * kD;
    hr[t]       = __float2half_rn(d0 * rs * lng[t]       + lnb[t]);
    hr[t + 256] = __float2half_rn(d1 * rs * lng[t + 256] + lnb[t + 256]);
    hr[t + 512] = __float2half_rn(d2 * rs * lng[t + 512] + lnb[t + 512]);
}

// ---------------- grouped GEMM (fp16 WMMA, 4-stage cp.async) ----------------
// FIRST=true:  A = gathered LN out (g_hbuf via g_perm), C = gelu(A*W1+b1) -> g_abuf (fp16)
// FIRST=false: A = g_abuf, C scattered: out[tok] = g_xbuf[tok] + A*W2+b2 (fp32)
// Wh is [E, Kdim, Ndim] row-major fp16 (matrix_b row_major -> no transpose needed).
template <bool FIRST>
__global__ void __launch_bounds__(256) gemm_wmma(
    const __half* __restrict__ Wh,
    const float* __restrict__ bias,
    float* __restrict__ dout,
    int Kdim, int Ndim)
{
    extern __shared__ __half sm[];
    __shared__ int row_tok[BM];

    const int tile = blockIdx.y;
    if (tile * BM >= g_off[kE]) return;
    const int n0 = blockIdx.x * BN;

    int e = 0;
#pragma unroll
    for (int i = 1; i <= kE; i++)
        if (tile * BM >= g_off[i]) e = i;

    const int tid = threadIdx.x;
    const int wid = tid >> 5, lane = tid & 31;
    const int wr = wid >> 1;   // 0..3 -> rows [wr*32, +32)
    const int wc = wid & 1;    // 0..1 -> cols [wc*64, +64)

    if (tid < BM) row_tok[tid] = g_perm[tile * BM + tid];
    __syncthreads();

    const __half* Wp = Wh + (size_t)e * Kdim * Ndim;
    const float*  bp = bias + (size_t)e * Ndim;

    auto fill = [&](int s, int ktile) {
        const int k0 = ktile * BK;
        __half* Ab = sm + s * STG_ELE;
        __half* Bb = Ab + A_ELE;
        // A tile: 128 rows x 32 halves (64B) = 4 chunks/row, 512 chunks
#pragma unroll
        for (int j = 0; j < 2; j++) {
            int idx = tid + j * 256;
            int r = idx >> 2, c = idx & 3;
            if (FIRST) {
                int tok = row_tok[r];
                const __half* src = g_hbuf + (size_t)(tok < 0 ? 0 : tok) * kD + k0 + c * 8;
                cp_async16(Ab + r * LDA + c * 8, src, tok >= 0 ? 16 : 0);
            } else {
                cp_async16(Ab + r * LDA + c * 8,
                           g_abuf + (size_t)(tile * BM + r) * kH + k0 + c * 8, 16);
            }
        }
        // B tile: 32 rows x 128 halves (256B) = 16 chunks/row, 512 chunks
#pragma unroll
        for (int j = 0; j < 2; j++) {
            int idx = tid + j * 256;
            int r = idx >> 4, c = idx & 15;
            cp_async16(Bb + r * LDB + c * 8,
                       Wp + (size_t)(k0 + r) * Ndim + n0 + c * 8, 16);
        }
    };

    wmma::fragment<wmma::accumulator, 16, 16, 16, float> acc[2][4];
#pragma unroll
    for (int i = 0; i < 2; i++)
#pragma unroll
        for (int j = 0; j < 4; j++) wmma::fill_fragment(acc[i][j], 0.0f);

    const int KT = Kdim / BK;
#pragma unroll
    for (int s = 0; s < NSTG - 1; s++) { fill(s, s); cp_commit(); }

    for (int it = 0; it < KT; ++it) {
        const int pf = it + NSTG - 1;
        if (pf < KT) fill(pf % NSTG, pf);
        cp_commit();                 // uniform group count
        cp_wait<NSTG - 1>();         // oldest (stage it) complete
        __syncthreads();

        const __half* Ab = sm + (it % NSTG) * STG_ELE;
        const __half* Bb = Ab + A_ELE;
#pragma unroll
        for (int ks = 0; ks < BK / 16; ks++) {
            wmma::fragment<wmma::matrix_a, 16, 16, 16, __half, wmma::row_major> af[2];
            wmma::fragment<wmma::matrix_b, 16, 16, 16, __half, wmma::row_major> bf[4];
#pragma unroll
            for (int i = 0; i < 2; i++)
                wmma::load_matrix_sync(af[i], &Ab[(wr * 32 + i * 16) * LDA + ks * 16], LDA);
#pragma unroll
            for (int jf = 0; jf < 4; jf++)
                wmma::load_matrix_sync(bf[jf], &Bb[(ks * 16) * LDB + wc * 64 + jf * 16], LDB);
#pragma unroll
            for (int i = 0; i < 2; i++)
#pragma unroll
                for (int jf = 0; jf < 4; jf++)
                    wmma::mma_sync(acc[i][jf], af[i], bf[jf], acc[i][jf]);
        }
        __syncthreads();
    }

    // ---- epilogue (stage smem reused as fp32 staging; mainloop fully synced) ----
    float* cstage = reinterpret_cast<float*>(sm);
    float* cw = cstage + wid * (16 * LDC_S);
    float* outp = dout ? dout : g_xbuf;

#pragma unroll
    for (int i = 0; i < 2; i++) {
#pragma unroll
        for (int jf = 0; jf < 4; jf++) {
            wmma::store_matrix_sync(cw, acc[i][jf], LDC_S, wmma::mem_row_major);
            __syncwarp();
            int r0 = wr * 32 + i * 16;
            int c0 = n0 + wc * 64 + jf * 16;
#pragma unroll
            for (int t = 0; t < 8; t++) {
                int lin = t * 32 + lane;  // 16 consecutive cols per half-warp
                int lr = lin >> 4, lc = lin & 15;
                float val = cw[lr * LDC_S + lc] + bp[c0 + lc];
                if (FIRST) {
                    g_abuf[(size_t)(tile * BM + r0 + lr) * kH + c0 + lc] =
                        __float2half_rn(gelu_exact(val));
                } else {
                    int tok = row_tok[r0 + lr];
                    if (tok >= 0) {
                        size_t o = (size_t)tok * kD + c0 + lc;
                        outp[o] = g_xbuf[o] + val;
                    }
                }
            }
            __syncwarp();
        }
    }
}

// ---------------- launch ----------------
extern "C" void kernel_launch(void* const* d_in, const int* in_sizes, int n_in,
                              void* d_out, int out_size) {
    const float* x   = (const float*)d_in[0];
    const int*   eix = (const int*)d_in[1];
    const float* W1  = (const float*)d_in[2];
    const float* b1  = (const float*)d_in[3];
    const float* W2  = (const float*)d_in[4];
    const float* b2  = (const float*)d_in[5];
    const float* lng = (const float*)d_in[6];
    const float* lnb = (const float*)d_in[7];
    float* out = (float*)d_out;

    cudaFuncSetAttribute(gemm_wmma<true>,
                         cudaFuncAttributeMaxDynamicSharedMemorySize, SMEM_BYTES);
    cudaFuncSetAttribute(gemm_wmma<false>,
                         cudaFuncAttributeMaxDynamicSharedMemorySize, SMEM_BYTES);

    copy_x<<<(kT * kD / 4) / 256, 256>>>((const float4*)x);
    route_init<<<(MAXROWS + 255) / 256, 256>>>();
    route_count<<<kT / 256, 256>>>(eix);
    route_offsets<<<1, 32>>>();
    route_scatter<<<kT / 256, 256>>>(eix);

    // fp32 -> fp16 weight conversion (no transpose needed: [K,N] row-major)
    constexpr int WN = kL * kE * kD * kH;  // elements per weight tensor (same for W1/W2)
    convert_w<<<(WN / 4) / 256, 256>>>((const float4*)W1, g_w1h);
    convert_w<<<(WN / 4) / 256, 256>>>((const float4*)W2, g_w2h);

    for (int l = 0; l < kL; l++) {
        ln_kernel<<<kT, 256>>>(lng + (size_t)l * kD, lnb + (size_t)l * kD);
        gemm_wmma<true><<<dim3(kH / BN, NT_MAX), 256, SMEM_BYTES>>>(
            g_w1h + (size_t)l * kE * kD * kH,
            b1 + (size_t)l * kE * kH,
            nullptr, kD, kH);
        gemm_wmma<false><<<dim3(kD / BN, NT_MAX), 256, SMEM_BYTES>>>(
            g_w2h + (size_t)l * kE * kH * kD,
            b2 + (size_t)l * kE * kD,
            (l == kL - 1) ? out : nullptr, kH, kD);
    }
}